// round 16
// baseline (speedup 1.0000x reference)
#include <cuda_runtime.h>

#define Ec   128
#define Wc   128
#define Vc   7
#define Sc   2048
#define Bc   16
#define GBLK 128                 // g blocks (one per e); + Bc final blocks = 144
#define NT   256

// Scratch (counters return to 0 at end of every run -> deterministic replays)
__device__ float d_g[Ec * Wc];   // g[e][k]
__device__ int   d_arrive;       // g blocks completed
__device__ int   d_done;         // final blocks completed

__device__ __forceinline__ int ld_acquire_gpu(const int* p) {
    int v;
    asm volatile("ld.acquire.gpu.global.b32 %0, [%1];" : "=r"(v) : "l"(p));
    return v;
}
__device__ __forceinline__ void red_release_gpu_add(int* p, int v) {
    asm volatile("red.release.gpu.global.add.s32 [%0], %1;" :: "l"(p), "r"(v));
}

__global__ void __launch_bounds__(NT, 1)
fused_kernel(const void* __restrict__ xraw,
             const float* __restrict__ emb,
             const float* __restrict__ fc_w,
             const float* __restrict__ fc_b,
             const float* __restrict__ out_w,
             const float* __restrict__ out_b,
             float* __restrict__ out) {
    const int blk = blockIdx.x;
    const int tid = threadIdx.x;
    const int wid = tid >> 5, lid = tid & 31;

    if (blk < GBLK) {
        // ===== g block e: warp w streams o-rows [16w,16w+16) as float4 =====
        const int e = blk;
        __shared__ float  s_w[Ec];
        __shared__ float4 sp4[8][32];            // per-warp k-quad partials

        // fire the 16 LDG.128 BEFORE the s_w barrier (barrier hides under them)
        const float4* fw4 = (const float4*)fc_w + e * 32 + lid;
        const int o0 = wid * 16;
        float4 vals[16];
#pragma unroll
        for (int u = 0; u < 16; u++)
            vals[u] = fw4[(size_t)(o0 + u) * 4096];   // 16 LDG.128 in flight

        if (tid < Ec) s_w[tid] = out_w[tid];
        __syncthreads();

        float ax = 0.f, ay = 0.f, az = 0.f, aw = 0.f;
#pragma unroll
        for (int u = 0; u < 16; u++) {
            const float wo = s_w[o0 + u];
            ax = fmaf(wo, vals[u].x, ax);
            ay = fmaf(wo, vals[u].y, ay);
            az = fmaf(wo, vals[u].z, az);
            aw = fmaf(wo, vals[u].w, aw);
        }
        sp4[wid][lid] = make_float4(ax, ay, az, aw);
        __syncthreads();

        if (tid < Wc) {                           // k = tid
            const float* spf = (const float*)sp4; // [8][128] floats
            float s = 0.0f;
#pragma unroll
            for (int w = 0; w < 8; w++)
                s += spf[w * 128 + tid];          // bank = k%32: conflict-free
            d_g[e * Wc + tid] = s;
            // only the 4 combining warps need ordering before the release
            asm volatile("bar.sync 1, 128;" ::: "memory");
            if (tid == 0) red_release_gpu_add(&d_arrive, 1);  // cumulative release
        }
        return;
    }

    // ========== final block: batch b = blk - GBLK (self-contained) ==========
    const int b = blk - GBLK;
    const int k = tid & 127;             // window tap
    const int h = tid >> 7;              // e-half
    __shared__ int   sred[NT / 32];
    __shared__ float sfl[NT / 32];
    __shared__ int   s_tok[Wc];
    __shared__ float s_emb[8 * 129];     // row 7 zeroed (pad sentinel)

    // hoisted: bias term for the fold (L2 latency hides under g-phase)
    float bias = (h == 0) ? out_w[k] * fc_b[k] : 0.0f;

    for (int i = tid; i < 8 * Ec; i += NT)
        s_emb[(i >> 7) * 129 + (i & 127)] = (i < Vc * Ec) ? emb[i] : 0.0f;

    // dtype detection: tokens in [0,7) => int64 iff odd 32-bit words are zero.
    // 512 words = 256 odd samples: P(all zero | int32) = (1/7)^256 ~ 0.
    const int* xw = (const int*)xraw;
    int any = 0;
    if (tid < 256) {
        int v = xw[tid * 2 + 1];
        any = (v != 0);
    }
    any = __any_sync(0xffffffffu, any) ? 1 : 0;
    if (lid == 0) sred[wid] = any;
    __syncthreads();
    int is32 = 0;
#pragma unroll
    for (int i = 0; i < NT / 32; i++) is32 |= sred[i];
    __syncthreads();

    // count non-pad tokens in row b (vectorized)
    int cnt = 0;
    if (is32) {
        const int4* xr = (const int4*)((const int*)xraw + b * Sc);   // 512 int4
#pragma unroll
        for (int s = 0; s < 2; s++) {
            int4 v = xr[tid + s * NT];
            cnt += (v.x != 0) + (v.y != 0) + (v.z != 0) + (v.w != 0);
        }
    } else {
        const longlong2* xr =
            (const longlong2*)((const long long*)xraw + b * Sc);     // 1024 ll2
#pragma unroll
        for (int s = 0; s < 4; s++) {
            longlong2 v = xr[tid + s * NT];
            cnt += (v.x != 0) + (v.y != 0);
        }
    }
#pragma unroll
    for (int off = 16; off; off >>= 1)
        cnt += __shfl_down_sync(0xffffffffu, cnt, off);
    if (lid == 0) sred[wid] = cnt;
    __syncthreads();
    int t = -1;
#pragma unroll
    for (int i = 0; i < NT / 32; i++) t += sred[i];

    // window tokens -> shared (sentinel 7 = pad -> zero emb row)
    if (tid < Wc) {
        const int p = t - (Wc - 1) + tid;
        int tok = Vc;
        if (p >= 0)
            tok = is32 ? ((const int*)xraw)[b * Sc + p]
                       : (int)((const long long*)xraw)[b * Sc + p];
        s_tok[tid] = tok;
    }
    __syncthreads();

    // hoisted epilogue bases (tok known pre-spin)
    const int tok = s_tok[k];
    const float* er = &s_emb[tok * 129 + h * 64];
    const float* gp = &d_g[(h * 64) * Wc + k];

    // per-warp spin with acquire: each warp fires its loads the moment it wakes
    if (lid == 0)
        while (ld_acquire_gpu(&d_arrive) < GBLK) __nanosleep(16);
    __syncwarp();

    // thread (k,h): tap k, e in [64h,64h+64); all 64 coalesced loads staged,
    // 4 interleaved accumulator chains (short dependent-FMA path)
    float a0 = bias, a1 = 0.f, a2 = 0.f, a3 = 0.f;
    {
        float vals[64];
#pragma unroll
        for (int u = 0; u < 64; u++)
            vals[u] = gp[u * Wc];                 // one L2 round trip
#pragma unroll
        for (int u = 0; u < 64; u += 4) {
            a0 = fmaf(er[u],     vals[u],     a0);
            a1 = fmaf(er[u + 1], vals[u + 1], a1);
            a2 = fmaf(er[u + 2], vals[u + 2], a2);
            a3 = fmaf(er[u + 3], vals[u + 3], a3);
        }
    }
    float acc = (a0 + a1) + (a2 + a3);

    // block reduction over all 256 threads
#pragma unroll
    for (int off = 16; off; off >>= 1)
        acc += __shfl_down_sync(0xffffffffu, acc, off);
    if (lid == 0) sfl[wid] = acc;
    __syncthreads();
    if (tid == 0) {
        float s = 0.0f;
#pragma unroll
        for (int i = 0; i < NT / 32; i++) s += sfl[i];
        out[b] = s + out_b[0];
    }

    // reset counters for next graph replay
    __syncthreads();
    if (tid == 0) {
        int d = atomicAdd(&d_done, 1);
        if (d == Bc - 1) {      // last final block; every spin already released
            d_arrive = 0;
            d_done   = 0;
            __threadfence();
        }
    }
}

extern "C" void kernel_launch(void* const* d_in, const int* in_sizes, int n_in,
                              void* d_out, int out_size) {
    const void*  x     = d_in[0];                      // [16,2048] int64 or int32
    const float* emb   = (const float*)d_in[1];        // [7,128]
    const float* fc_w  = (const float*)d_in[2];        // [128,16384]
    const float* fc_b  = (const float*)d_in[3];        // [128]
    const float* out_w = (const float*)d_in[4];        // [1,128]
    const float* out_b = (const float*)d_in[5];        // [1]
    float* out = (float*)d_out;                        // [16]

    fused_kernel<<<GBLK + Bc, NT>>>(x, emb, fc_w, fc_b, out_w, out_b, out);
}

// round 17
// speedup vs baseline: 1.2399x; 1.2399x over previous
#include <cuda_runtime.h>

#define Ec   128
#define Wc   128
#define Vc   7
#define Sc   2048
#define Bc   16
#define GBLK 128                 // g blocks (one per e); + Bc final blocks = 144
#define NT   256

// Scratch (counters return to 0 at end of every run -> deterministic replays)
__device__ float d_g[Ec * Wc];   // g[e][k]
__device__ int   d_arrive;       // g blocks completed
__device__ int   d_done;         // final blocks completed

__device__ __forceinline__ int ld_acquire_gpu(const int* p) {
    int v;
    asm volatile("ld.acquire.gpu.global.b32 %0, [%1];" : "=r"(v) : "l"(p));
    return v;
}
__device__ __forceinline__ void red_release_gpu_add(int* p, int v) {
    asm volatile("red.release.gpu.global.add.s32 [%0], %1;" :: "l"(p), "r"(v));
}

__global__ void __launch_bounds__(NT, 1)
fused_kernel(const void* __restrict__ xraw,
             const float* __restrict__ emb,
             const float* __restrict__ fc_w,
             const float* __restrict__ fc_b,
             const float* __restrict__ out_w,
             const float* __restrict__ out_b,
             float* __restrict__ out) {
    const int blk = blockIdx.x;
    const int tid = threadIdx.x;
    const int wid = tid >> 5, lid = tid & 31;

    if (blk < GBLK) {
        // ===== g block e: warp w streams o-rows [16w,16w+16) as float4 =====
        const int e = blk;
        __shared__ float  s_w[Ec];
        __shared__ float4 sp4[8][32];            // per-warp k-quad partials

        // fire the 16 LDG.128 BEFORE the s_w barrier (barrier hides under them)
        const float4* fw4 = (const float4*)fc_w + e * 32 + lid;
        const int o0 = wid * 16;
        float4 vals[16];
#pragma unroll
        for (int u = 0; u < 16; u++)
            vals[u] = fw4[(size_t)(o0 + u) * 4096];   // 16 LDG.128 in flight

        if (tid < Ec) s_w[tid] = out_w[tid];
        __syncthreads();

        float ax = 0.f, ay = 0.f, az = 0.f, aw = 0.f;
#pragma unroll
        for (int u = 0; u < 16; u++) {
            const float wo = s_w[o0 + u];
            ax = fmaf(wo, vals[u].x, ax);
            ay = fmaf(wo, vals[u].y, ay);
            az = fmaf(wo, vals[u].z, az);
            aw = fmaf(wo, vals[u].w, aw);
        }
        sp4[wid][lid] = make_float4(ax, ay, az, aw);
        __syncthreads();

        if (tid < Wc) {                           // k = tid
            const float* spf = (const float*)sp4; // [8][128] floats
            float s = 0.0f;
#pragma unroll
            for (int w = 0; w < 8; w++)
                s += spf[w * 128 + tid];          // bank = k%32: conflict-free
            d_g[e * Wc + tid] = s;
            // only the 4 combining warps need ordering before the release
            asm volatile("bar.sync 1, 128;" ::: "memory");
            if (tid == 0) red_release_gpu_add(&d_arrive, 1);  // cumulative release
        }
        return;
    }

    // ========== final block: batch b = blk - GBLK (self-contained) ==========
    const int b = blk - GBLK;
    const int k = tid & 127;             // window tap
    const int h = tid >> 7;              // e-half
    __shared__ int   sred[NT / 32];
    __shared__ float sfl[NT / 32];
    __shared__ int   s_tok[Wc];
    __shared__ float s_emb[8 * 129];     // row 7 zeroed (pad sentinel)

    // hoisted: bias term for the fold (L2 latency hides under g-phase)
    float bias = (h == 0) ? out_w[k] * fc_b[k] : 0.0f;

    for (int i = tid; i < 8 * Ec; i += NT)
        s_emb[(i >> 7) * 129 + (i & 127)] = (i < Vc * Ec) ? emb[i] : 0.0f;

    // dtype detection: tokens in [0,7) => int64 iff odd 32-bit words are zero.
    // 512 words = 256 odd samples: P(all zero | int32) = (1/7)^256 ~ 0.
    const int* xw = (const int*)xraw;
    int any = 0;
    if (tid < 256) {
        int v = xw[tid * 2 + 1];
        any = (v != 0);
    }
    any = __any_sync(0xffffffffu, any) ? 1 : 0;
    if (lid == 0) sred[wid] = any;
    __syncthreads();
    int is32 = 0;
#pragma unroll
    for (int i = 0; i < NT / 32; i++) is32 |= sred[i];
    __syncthreads();

    // count non-pad tokens in row b (vectorized)
    int cnt = 0;
    if (is32) {
        const int4* xr = (const int4*)((const int*)xraw + b * Sc);   // 512 int4
#pragma unroll
        for (int s = 0; s < 2; s++) {
            int4 v = xr[tid + s * NT];
            cnt += (v.x != 0) + (v.y != 0) + (v.z != 0) + (v.w != 0);
        }
    } else {
        const longlong2* xr =
            (const longlong2*)((const long long*)xraw + b * Sc);     // 1024 ll2
#pragma unroll
        for (int s = 0; s < 4; s++) {
            longlong2 v = xr[tid + s * NT];
            cnt += (v.x != 0) + (v.y != 0);
        }
    }
#pragma unroll
    for (int off = 16; off; off >>= 1)
        cnt += __shfl_down_sync(0xffffffffu, cnt, off);
    if (lid == 0) sred[wid] = cnt;
    __syncthreads();
    int t = -1;
#pragma unroll
    for (int i = 0; i < NT / 32; i++) t += sred[i];

    // window tokens -> shared (sentinel 7 = pad -> zero emb row)
    if (tid < Wc) {
        const int p = t - (Wc - 1) + tid;
        int tok = Vc;
        if (p >= 0)
            tok = is32 ? ((const int*)xraw)[b * Sc + p]
                       : (int)((const long long*)xraw)[b * Sc + p];
        s_tok[tid] = tok;
    }
    __syncthreads();

    // hoisted epilogue bases (tok known pre-spin)
    const int tok = s_tok[k];
    const float* er = &s_emb[tok * 129 + h * 64];
    const float* gp = &d_g[(h * 64) * Wc + k];

    // per-warp spin with acquire: each warp fires its loads the moment it wakes
    if (lid == 0)
        while (ld_acquire_gpu(&d_arrive) < GBLK) __nanosleep(16);
    __syncwarp();

    // thread (k,h): tap k, e in [64h,64h+64); all 64 coalesced loads staged
    float acc = bias;
    {
        float vals[64];
#pragma unroll
        for (int u = 0; u < 64; u++)
            vals[u] = gp[u * Wc];                 // one L2 round trip
#pragma unroll
        for (int u = 0; u < 64; u++)
            acc = fmaf(er[u], vals[u], acc);
    }

    // block reduction over all 256 threads
#pragma unroll
    for (int off = 16; off; off >>= 1)
        acc += __shfl_down_sync(0xffffffffu, acc, off);
    if (lid == 0) sfl[wid] = acc;
    __syncthreads();
    if (tid == 0) {
        float s = 0.0f;
#pragma unroll
        for (int i = 0; i < NT / 32; i++) s += sfl[i];
        out[b] = s + out_b[0];
    }

    // reset counters for next graph replay
    __syncthreads();
    if (tid == 0) {
        int d = atomicAdd(&d_done, 1);
        if (d == Bc - 1) {      // last final block; every spin already released
            d_arrive = 0;
            d_done   = 0;
            __threadfence();
        }
    }
}

extern "C" void kernel_launch(void* const* d_in, const int* in_sizes, int n_in,
                              void* d_out, int out_size) {
    const void*  x     = d_in[0];                      // [16,2048] int64 or int32
    const float* emb   = (const float*)d_in[1];        // [7,128]
    const float* fc_w  = (const float*)d_in[2];        // [128,16384]
    const float* fc_b  = (const float*)d_in[3];        // [128]
    const float* out_w = (const float*)d_in[4];        // [1,128]
    const float* out_b = (const float*)d_in[5];        // [1]
    float* out = (float*)d_out;                        // [16]

    fused_kernel<<<GBLK + Bc, NT>>>(x, emb, fc_w, fc_b, out_w, out_b, out);
}